// round 13
// baseline (speedup 1.0000x reference)
#include <cuda_runtime.h>
#include <cuda_fp16.h>
#include <cstdint>
#include <cstddef>

// Problem constants
#define BATCH   2
#define SEQ     2048
#define DIM     1024
#define HEADS   16
#define DHEAD   64
#define INNER   1024
#define ROWS    (BATCH*SEQ)   // 4096
#define QKV_N   (3*INNER)     // 3072
#define EPS     1e-5f
#define QSCALE  0.125f

// ---------------- scratch (static device globals) ---------------------------
__device__ __half g_xn  [(size_t)ROWS * DIM  ];
__device__ __half g_qkv [(size_t)ROWS * QKV_N];
__device__ __half g_att [(size_t)ROWS * INNER];
__device__ float  g_proj[(size_t)ROWS * DIM  ];
__device__ __half g_wq  [(size_t)QKV_N * DIM ];   // transposed [N][K] fp16
__device__ __half g_wo  [(size_t)DIM * INNER ];   // transposed [N][K] fp16

// ---------------- helpers ----------------------------------------------------
__device__ __forceinline__ uint32_t smem_u32(const void* p) {
    uint32_t a;
    asm("{ .reg .u64 t; cvta.to.shared.u64 t, %1; cvt.u32.u64 %0, t; }"
        : "=r"(a) : "l"(p));
    return a;
}
__device__ __forceinline__ void cpa16(uint32_t dst, const void* src) {
    asm volatile("cp.async.cg.shared.global [%0], [%1], 16;" :: "r"(dst), "l"(src));
}
__device__ __forceinline__ void cpa_commit() {
    asm volatile("cp.async.commit_group;" ::: "memory");
}
template<int N> __device__ __forceinline__ void cpa_wait() {
    asm volatile("cp.async.wait_group %0;" :: "n"(N) : "memory");
}
__device__ __forceinline__ void ldsm_x4(uint32_t addr, uint32_t& r0, uint32_t& r1,
                                        uint32_t& r2, uint32_t& r3) {
    asm volatile("ldmatrix.sync.aligned.m8n8.x4.shared.b16 {%0,%1,%2,%3}, [%4];"
                 : "=r"(r0), "=r"(r1), "=r"(r2), "=r"(r3) : "r"(addr));
}
__device__ __forceinline__ void ldsm_x4_t(uint32_t addr, uint32_t& r0, uint32_t& r1,
                                          uint32_t& r2, uint32_t& r3) {
    asm volatile("ldmatrix.sync.aligned.m8n8.x4.trans.shared.b16 {%0,%1,%2,%3}, [%4];"
                 : "=r"(r0), "=r"(r1), "=r"(r2), "=r"(r3) : "r"(addr));
}
__device__ __forceinline__ void mma_f16(float& d0, float& d1, float& d2, float& d3,
                                        uint32_t a0, uint32_t a1, uint32_t a2, uint32_t a3,
                                        uint32_t b0, uint32_t b1) {
    asm volatile("mma.sync.aligned.m16n8k16.row.col.f32.f16.f16.f32 "
                 "{%0,%1,%2,%3},{%4,%5,%6,%7},{%8,%9},{%0,%1,%2,%3};"
                 : "+f"(d0), "+f"(d1), "+f"(d2), "+f"(d3)
                 : "r"(a0), "r"(a1), "r"(a2), "r"(a3), "r"(b0), "r"(b1));
}

// ---------------- LayerNorm ---------------------------------------------------
__device__ __forceinline__ float4 ln_compute(const float* __restrict__ in,
                                             const float* __restrict__ gamma,
                                             const float* __restrict__ beta)
{
    const int row = blockIdx.x;
    const float* xr = in + (size_t)row * DIM;
    const int t = threadIdx.x;

    float4 xv = *(const float4*)(xr + t * 4);
    float sum = xv.x + xv.y + xv.z + xv.w;
    float sq  = xv.x*xv.x + xv.y*xv.y + xv.z*xv.z + xv.w*xv.w;
    #pragma unroll
    for (int o = 16; o > 0; o >>= 1) {
        sum += __shfl_xor_sync(0xffffffffu, sum, o);
        sq  += __shfl_xor_sync(0xffffffffu, sq,  o);
    }
    __shared__ float s1[8], s2[8];
    const int warp = t >> 5;
    if ((t & 31) == 0) { s1[warp] = sum; s2[warp] = sq; }
    __syncthreads();
    float tot = 0.f, totq = 0.f;
    #pragma unroll
    for (int w = 0; w < 8; w++) { tot += s1[w]; totq += s2[w]; }
    const float mean = tot * (1.0f / DIM);
    const float var  = totq * (1.0f / DIM) - mean * mean;
    const float inv  = rsqrtf(var + EPS);
    float4 gv = *(const float4*)(gamma + t * 4);
    float4 bv = *(const float4*)(beta  + t * 4);
    float4 ov;
    ov.x = (xv.x - mean) * inv * gv.x + bv.x;
    ov.y = (xv.y - mean) * inv * gv.y + bv.y;
    ov.z = (xv.z - mean) * inv * gv.z + bv.z;
    ov.w = (xv.w - mean) * inv * gv.w + bv.w;
    return ov;
}

__global__ __launch_bounds__(256) void ln1_kernel(const float* __restrict__ x,
                                                  const float* __restrict__ g,
                                                  const float* __restrict__ b)
{
    float4 ov = ln_compute(x, g, b);
    __half2* dst = (__half2*)(g_xn + (size_t)blockIdx.x * DIM + threadIdx.x * 4);
    dst[0] = __floats2half2_rn(ov.x, ov.y);
    dst[1] = __floats2half2_rn(ov.z, ov.w);
}
__global__ __launch_bounds__(256) void ln2_kernel(const float* __restrict__ g,
                                                  const float* __restrict__ b,
                                                  float* __restrict__ out)
{
    float4 ov = ln_compute(g_proj, g, b);
    *(float4*)(out + (size_t)blockIdx.x * DIM + threadIdx.x * 4) = ov;
}

// ---------------- weight transpose+convert: f32 [R][C] -> f16 [C][R] ---------
__global__ __launch_bounds__(256) void transpose_h_kernel(const float* __restrict__ in,
                                                          __half* __restrict__ out,
                                                          int R, int C)
{
    __shared__ float t[32][33];
    const int c0 = blockIdx.x * 32, r0 = blockIdx.y * 32;
    const int tx = threadIdx.x & 31, ty = threadIdx.x >> 5;
    #pragma unroll
    for (int i = ty; i < 32; i += 8)
        t[i][tx] = in[(size_t)(r0 + i) * C + c0 + tx];
    __syncthreads();
    #pragma unroll
    for (int i = ty; i < 32; i += 8)
        out[(size_t)(c0 + i) * R + r0 + tx] = __float2half_rn(t[tx][i]);
}

// ---------------- fp16 HMMA GEMM (round-11 config, best measured) ------------
// BM=128, BN=256, BK=32 halves; 512 threads = 16 warps (4x4); warp tile 32x64.
#define GBM 128
#define GBN 256
#define GBK 32
#define A_STH 40
#define B_STH 40
#define A_FLH (128 * A_STH)            // 5120 halves
#define B_FLH (256 * B_STH)            // 10240 halves
#define G_STG_H (A_FLH + B_FLH)        // 15360 halves / stage
#define GEMM_SMEM (3 * G_STG_H * 2)    // 92160 B

template<typename OutT>
__global__ __launch_bounds__(512, 1) void gemm_f16_kernel(
    const __half* __restrict__ A, const __half* __restrict__ BT,
    OutT* __restrict__ C, int Ntot, int K)
{
    extern __shared__ __half smh[];
    const uint32_t smu = smem_u32(smh);

    const int tid = threadIdx.x;
    const int lane = tid & 31;
    const int wid = tid >> 5;             // 0..15
    const int warpM = wid >> 2;           // 0..3
    const int warpN = wid & 3;            // 0..3
    const int bm = blockIdx.y * GBM;
    const int bn = blockIdx.x * GBN;
    const int NCH = K / GBK;
    const int grp = lane >> 3, lr = lane & 7;

    const int am = tid >> 2;              // 0..127
    const int ac = (tid & 3) * 8;
    const __half* aG = A + (size_t)(bm + am) * K + ac;
    const uint32_t aDst = smu + (uint32_t)(am * A_STH + ac) * 2;
    const int bnr = tid >> 1;             // 0..255
    const int bc  = (tid & 1) * 16;
    const __half* bG = BT + (size_t)(bn + bnr) * K + bc;
    const uint32_t bDst = smu + (uint32_t)(A_FLH + bnr * B_STH + bc) * 2;

    float acc[2][8][4];
    #pragma unroll
    for (int i = 0; i < 2; i++)
        #pragma unroll
        for (int j = 0; j < 8; j++)
            #pragma unroll
            for (int r = 0; r < 4; r++) acc[i][j][r] = 0.f;

    #define GEMM_ISSUE(c, stg) do {                                           \
        const uint32_t _so = (uint32_t)(stg) * (G_STG_H * 2);                  \
        cpa16(aDst + _so, aG + (c) * GBK);                                     \
        const __half* _bg = bG + (c) * GBK;                                    \
        cpa16(bDst + _so,      _bg);                                           \
        cpa16(bDst + _so + 16, _bg + 8);                                       \
    } while (0)

    GEMM_ISSUE(0, 0); cpa_commit();
    GEMM_ISSUE(1, 1); cpa_commit();

    int stg = 0;
    for (int c = 0; c < NCH; c++) {
        if (c == NCH - 1) cpa_wait<0>(); else cpa_wait<1>();
        __syncthreads();

        {
            int nstg = stg + 2; if (nstg >= 3) nstg -= 3;
            if (c + 2 < NCH) GEMM_ISSUE(c + 2, nstg);
            cpa_commit();
        }

        const uint32_t aS = smu + (uint32_t)(stg * G_STG_H) * 2;
        const uint32_t bS = aS + A_FLH * 2;

        #pragma unroll
        for (int ks = 0; ks < 2; ks++) {
            uint32_t a[2][4];
            #pragma unroll
            for (int mt = 0; mt < 2; mt++) {
                int row = warpM * 32 + mt * 16 + lr + (grp & 1) * 8;
                int kc  = ks * 16 + (grp >> 1) * 8;
                ldsm_x4(aS + (uint32_t)(row * A_STH + kc) * 2,
                        a[mt][0], a[mt][1], a[mt][2], a[mt][3]);
            }
            uint32_t bb[4][4];
            #pragma unroll
            for (int np = 0; np < 4; np++) {
                int rn = warpN * 64 + np * 16 + lr + (grp >> 1) * 8;
                int kc = ks * 16 + (grp & 1) * 8;
                ldsm_x4(bS + (uint32_t)(rn * B_STH + kc) * 2,
                        bb[np][0], bb[np][1], bb[np][2], bb[np][3]);
            }
            #pragma unroll
            for (int mt = 0; mt < 2; mt++)
                #pragma unroll
                for (int np = 0; np < 4; np++)
                    #pragma unroll
                    for (int s = 0; s < 2; s++)
                        mma_f16(acc[mt][np*2+s][0], acc[mt][np*2+s][1],
                                acc[mt][np*2+s][2], acc[mt][np*2+s][3],
                                a[mt][0], a[mt][1], a[mt][2], a[mt][3],
                                bb[np][2*s], bb[np][2*s+1]);
        }

        if (++stg == 3) stg = 0;
    }

    #pragma unroll
    for (int mt = 0; mt < 2; mt++) {
        #pragma unroll
        for (int nt = 0; nt < 8; nt++) {
            const int row = bm + warpM * 32 + mt * 16 + (lane >> 2);
            const int col = bn + warpN * 64 + nt * 8 + (lane & 3) * 2;
            if (sizeof(OutT) == 2) {
                __half2* p0 = (__half2*)((__half*)C + (size_t)row * Ntot + col);
                __half2* p1 = (__half2*)((__half*)C + (size_t)(row + 8) * Ntot + col);
                *p0 = __floats2half2_rn(acc[mt][nt][0], acc[mt][nt][1]);
                *p1 = __floats2half2_rn(acc[mt][nt][2], acc[mt][nt][3]);
            } else {
                *(float2*)((float*)C + (size_t)row * Ntot + col) =
                    make_float2(acc[mt][nt][0], acc[mt][nt][1]);
                *(float2*)((float*)C + (size_t)(row + 8) * Ntot + col) =
                    make_float2(acc[mt][nt][2], acc[mt][nt][3]);
            }
        }
    }
    #undef GEMM_ISSUE
}

// ---------------- fp16 tensor-core causal ReLU attention ---------------------
// 256-query tile, 512 threads (16 warps x 16 rows); KEY TILES OF 128.
// 3-buffer K+V ring; one barrier per 128-key tile (half the rounds of r11).
// S computed in two 64-col halves (keeps sacc at 32 regs).
// Warp group g=wid>>4? no: g = wid>>2 (0..3) owns 64 query rows; its diagonal
// key tile kt_w = 2*qt4 + (g>=2); skip kt > kt_w; mask elementwise at kt==kt_w.
#define AQ_STH 72
#define AK_STH 72
#define AV_STH 72
#define AS_STH 136
#define KBUF_H (128 * AK_STH)           // 9216 halves
#define VBUF_H (128 * AV_STH)           // 9216 halves
#define OFFH_Q 0                        // 256*72  = 18432
#define OFFH_K 18432                    // 3*9216  = 27648
#define OFFH_V 46080                    // 3*9216  = 27648
#define OFFH_S 73728                    // 256*136 = 34816
#define ATTN_H 108544
#define ATTN_SMEM (ATTN_H * 2)          // 217088 B

__global__ __launch_bounds__(512, 1) void attn_mma_kernel()
{
    extern __shared__ __half smh[];
    const uint32_t smu = smem_u32(smh);
    const int tid  = threadIdx.x;
    const int lane = tid & 31;
    const int wid  = tid >> 5;            // 0..15
    const int ly = lane >> 2;
    const int lx = lane & 3;
    const int grp = lane >> 3, lr = lane & 7;

    const int qt4 = 7 - blockIdx.x;       // longest tiles first
    const int bh = blockIdx.y;
    const int b  = bh >> 4;
    const int h  = bh & 15;
    const int qi0 = qt4 * 256;
    const int kt_last = 2 * qt4 + 1;                 // 128-key tiles
    const int kt_diag = 2 * qt4 + ((wid >> 2) >= 2 ? 1 : 0);

    const __half* qbase = g_qkv + (size_t)b * SEQ * QKV_N + h * DHEAD;
    const __half* kbase = qbase + INNER;
    const __half* vbase = qbase + 2 * INNER;

    const int ldr = tid >> 2;             // 0..127 (K/V staging row)
    const int ldc = (tid & 3) * 16;       // 16 halves (2 cpa16) per thread

    #define ISSUE_KV(kt_, buf_) do {                                            \
        const __half* _sk = kbase + (size_t)((kt_) * 128 + ldr) * QKV_N + ldc;   \
        uint32_t _dk = smu + (uint32_t)(OFFH_K + (buf_) * KBUF_H + ldr * AK_STH + ldc) * 2; \
        cpa16(_dk, _sk); cpa16(_dk + 16, _sk + 8);                               \
        const __half* _sv = vbase + (size_t)((kt_) * 128 + ldr) * QKV_N + ldc;   \
        uint32_t _dv = smu + (uint32_t)(OFFH_V + (buf_) * VBUF_H + ldr * AV_STH + ldc) * 2; \
        cpa16(_dv, _sv); cpa16(_dv + 16, _sv + 8);                               \
    } while (0)

    // stage Q (256 rows; unscaled fp16; scale applied in S epilogue)
    {
        const int qr = tid >> 1;          // 0..255
        const int qc = (tid & 1) * 32;
        const __half* src = qbase + (size_t)(qi0 + qr) * QKV_N + qc;
        uint32_t dst = smu + (uint32_t)(OFFH_Q + qr * AQ_STH + qc) * 2;
        #pragma unroll
        for (int j = 0; j < 4; j++) cpa16(dst + j * 16, src + j * 8);
    }
    ISSUE_KV(0, 0); cpa_commit();
    if (kt_last >= 1) ISSUE_KV(1, 1);
    cpa_commit();

    float oacc[8][4];
    #pragma unroll
    for (int nt = 0; nt < 8; nt++)
        #pragma unroll
        for (int r = 0; r < 4; r++) oacc[nt][r] = 0.f;

    __half* shw = smh + OFFH_S + (wid * 16 + ly) * AS_STH;
    const int qrow = qi0 + wid * 16 + ly;

    int stg = 0;
    for (int kt = 0; kt <= kt_last; kt++) {
        if (kt == kt_last) cpa_wait<0>(); else cpa_wait<1>();
        __syncthreads();                  // Q + K/V(kt) visible; stage kt-1 free

        {
            int nstg = stg + 2; if (nstg >= 3) nstg -= 3;
            if (kt + 2 <= kt_last) ISSUE_KV(kt + 2, nstg);
            cpa_commit();
        }

        if (kt <= kt_diag) {
            const uint32_t Kc = smu + (uint32_t)(OFFH_K + stg * KBUF_H) * 2;
            const uint32_t Qb = smu + (uint32_t)OFFH_Q * 2;

            // ---- S = Q K^T over 128 keys, computed in two 64-key halves
            #pragma unroll
            for (int half = 0; half < 2; half++) {
                float sacc[8][4];
                #pragma unroll
                for (int nt = 0; nt < 8; nt++)
                    #pragma unroll
                    for (int r = 0; r < 4; r++) sacc[nt][r] = 0.f;

                #pragma unroll
                for (int ks = 0; ks < 4; ks++) {
                    uint32_t a[4];
                    {
                        int row = wid * 16 + lr + (grp & 1) * 8;
                        int kc  = ks * 16 + (grp >> 1) * 8;
                        ldsm_x4(Qb + (uint32_t)(row * AQ_STH + kc) * 2,
                                a[0], a[1], a[2], a[3]);
                    }
                    #pragma unroll
                    for (int np = 0; np < 4; np++) {
                        uint32_t bb[4];
                        int rn = half * 64 + np * 16 + lr + (grp >> 1) * 8;
                        int kc = ks * 16 + (grp & 1) * 8;
                        ldsm_x4(Kc + (uint32_t)(rn * AK_STH + kc) * 2,
                                bb[0], bb[1], bb[2], bb[3]);
                        #pragma unroll
                        for (int s = 0; s < 2; s++)
                            mma_f16(sacc[np*2+s][0], sacc[np*2+s][1],
                                    sacc[np*2+s][2], sacc[np*2+s][3],
                                    a[0], a[1], a[2], a[3], bb[2*s], bb[2*s+1]);
                    }
                }

                // ---- scale+relu (+ mask on diagonal tile), fp16 -> smem S
                __half* sh = shw + half * 64;
                if (kt < kt_diag) {
                    #pragma unroll
                    for (int nt = 0; nt < 8; nt++) {
                        float v0 = fmaxf(sacc[nt][0], 0.f) * QSCALE;
                        float v1 = fmaxf(sacc[nt][1], 0.f) * QSCALE;
                        float v2 = fmaxf(sacc[nt][2], 0.f) * QSCALE;
                        float v3 = fmaxf(sacc[nt][3], 0.f) * QSCALE;
                        *(__half2*)(sh + nt * 8 + 2 * lx) = __floats2half2_rn(v0, v1);
                        *(__half2*)(sh + 8 * AS_STH + nt * 8 + 2 * lx) = __floats2half2_rn(v2, v3);
                    }
                } else {
                    #pragma unroll
                    for (int nt = 0; nt < 8; nt++) {
                        int j0 = kt * 128 + half * 64 + nt * 8 + 2 * lx;
                        float v0 = (j0     <= qrow    ) ? fmaxf(sacc[nt][0], 0.f) * QSCALE : 0.f;
                        float v1 = (j0 + 1 <= qrow    ) ? fmaxf(sacc[nt][1], 0.f) * QSCALE : 0.f;
                        float v2 = (j0     <= qrow + 8) ? fmaxf(sacc[nt][2], 0.f) * QSCALE : 0.f;
                        float v3 = (j0 + 1 <= qrow + 8) ? fmaxf(sacc[nt][3], 0.f) * QSCALE : 0.f;
                        *(__half2*)(sh + nt * 8 + 2 * lx) = __floats2half2_rn(v0, v1);
                        *(__half2*)(sh + 8 * AS_STH + nt * 8 + 2 * lx) = __floats2half2_rn(v2, v3);
                    }
                }
            }
            __syncwarp();                 // S rows are warp-private

            // ---- O += S*V over 128 keys (8 ks of 16)
            const uint32_t Sb = smu + (uint32_t)OFFH_S * 2;
            const uint32_t Vc = smu + (uint32_t)(OFFH_V + stg * VBUF_H) * 2;
            #pragma unroll
            for (int ks = 0; ks < 8; ks++) {
                uint32_t a[4];
                {
                    int row = wid * 16 + lr + (grp & 1) * 8;
                    int kc  = ks * 16 + (grp >> 1) * 8;
                    ldsm_x4(Sb + (uint32_t)(row * AS_STH + kc) * 2,
                            a[0], a[1], a[2], a[3]);
                }
                #pragma unroll
                for (int np = 0; np < 4; np++) {
                    uint32_t bb[4];
                    int kr = ks * 16 + lr + (grp & 1) * 8;
                    int nc = np * 16 + (grp >> 1) * 8;
                    ldsm_x4_t(Vc + (uint32_t)(kr * AV_STH + nc) * 2,
                              bb[0], bb[1], bb[2], bb[3]);
                    #pragma unroll
                    for (int s = 0; s < 2; s++)
                        mma_f16(oacc[np*2+s][0], oacc[np*2+s][1],
                                oacc[np*2+s][2], oacc[np*2+s][3],
                                a[0], a[1], a[2], a[3], bb[2*s], bb[2*s+1]);
                }
            }
        }

        if (++stg == 3) stg = 0;
    }

    // ---- store O as fp16 (feeds fp16 out-projection)
    __half* ob = g_att + (size_t)(b * SEQ + qi0 + wid * 16 + ly) * INNER + h * DHEAD;
    #pragma unroll
    for (int nt = 0; nt < 8; nt++) {
        *(__half2*)(ob + nt * 8 + 2 * lx) =
            __floats2half2_rn(oacc[nt][0], oacc[nt][1]);
        *(__half2*)(ob + (size_t)8 * INNER + nt * 8 + 2 * lx) =
            __floats2half2_rn(oacc[nt][2], oacc[nt][3]);
    }
    #undef ISSUE_KV
}

// ---------------- launch -----------------------------------------------------
extern "C" void kernel_launch(void* const* d_in, const int* in_sizes, int n_in,
                              void* d_out, int out_size)
{
    const float* x     = (const float*)d_in[0];
    const float* ln1_g = (const float*)d_in[1];
    const float* ln1_b = (const float*)d_in[2];
    const float* w_qkv = (const float*)d_in[3];
    const float* w_out = (const float*)d_in[4];
    const float* ln2_g = (const float*)d_in[5];
    const float* ln2_b = (const float*)d_in[6];
    float* out = (float*)d_out;

    cudaFuncSetAttribute(attn_mma_kernel,
                         cudaFuncAttributeMaxDynamicSharedMemorySize, ATTN_SMEM);
    cudaFuncSetAttribute(gemm_f16_kernel<__half>,
                         cudaFuncAttributeMaxDynamicSharedMemorySize, GEMM_SMEM);
    cudaFuncSetAttribute(gemm_f16_kernel<float>,
                         cudaFuncAttributeMaxDynamicSharedMemorySize, GEMM_SMEM);

    __half* wq;  cudaGetSymbolAddress((void**)&wq,  g_wq);
    __half* wo;  cudaGetSymbolAddress((void**)&wo,  g_wo);
    __half* xn;  cudaGetSymbolAddress((void**)&xn,  g_xn);
    __half* qkv; cudaGetSymbolAddress((void**)&qkv, g_qkv);
    __half* att; cudaGetSymbolAddress((void**)&att, g_att);
    float* proj; cudaGetSymbolAddress((void**)&proj, g_proj);

    ln1_kernel<<<ROWS, 256>>>(x, ln1_g, ln1_b);

    // weights: f32 [K][N] -> f16 [N][K]
    transpose_h_kernel<<<dim3(QKV_N / 32, DIM / 32), 256>>>(w_qkv, wq, DIM, QKV_N);
    transpose_h_kernel<<<dim3(DIM / 32, INNER / 32), 256>>>(w_out, wo, INNER, DIM);

    gemm_f16_kernel<__half><<<dim3(QKV_N / GBN, ROWS / GBM), 512, GEMM_SMEM>>>(
        xn, wq, qkv, QKV_N, DIM);

    attn_mma_kernel<<<dim3(8, BATCH * HEADS), 512, ATTN_SMEM>>>();

    gemm_f16_kernel<float><<<dim3(DIM / GBN, ROWS / GBM), 512, GEMM_SMEM>>>(
        att, wo, proj, DIM, INNER);

    ln2_kernel<<<ROWS, 256>>>(ln2_g, ln2_b, out);
}

// round 14
// speedup vs baseline: 1.1650x; 1.1650x over previous
#include <cuda_runtime.h>
#include <cuda_fp16.h>
#include <cstdint>
#include <cstddef>

// Problem constants
#define BATCH   2
#define SEQ     2048
#define DIM     1024
#define HEADS   16
#define DHEAD   64
#define INNER   1024
#define ROWS    (BATCH*SEQ)   // 4096
#define QKV_N   (3*INNER)     // 3072
#define EPS     1e-5f
#define QSCALE  0.125f

// ---------------- scratch (static device globals) ---------------------------
__device__ __half g_xn  [(size_t)ROWS * DIM  ];
__device__ __half g_qkv [(size_t)ROWS * QKV_N];
__device__ __half g_att [(size_t)ROWS * INNER];
__device__ float  g_proj[(size_t)ROWS * DIM  ];
__device__ __half g_wq  [(size_t)QKV_N * DIM ];   // transposed [N][K] fp16
__device__ __half g_wo  [(size_t)DIM * INNER ];   // transposed [N][K] fp16
__device__ unsigned int g_ticket;                  // attn work queue

#define ATTN_ITEMS 256   // 8 qt4 x 32 bh

// ---------------- helpers ----------------------------------------------------
__device__ __forceinline__ uint32_t smem_u32(const void* p) {
    uint32_t a;
    asm("{ .reg .u64 t; cvta.to.shared.u64 t, %1; cvt.u32.u64 %0, t; }"
        : "=r"(a) : "l"(p));
    return a;
}
__device__ __forceinline__ void cpa16(uint32_t dst, const void* src) {
    asm volatile("cp.async.cg.shared.global [%0], [%1], 16;" :: "r"(dst), "l"(src));
}
__device__ __forceinline__ void cpa_commit() {
    asm volatile("cp.async.commit_group;" ::: "memory");
}
template<int N> __device__ __forceinline__ void cpa_wait() {
    asm volatile("cp.async.wait_group %0;" :: "n"(N) : "memory");
}
__device__ __forceinline__ void ldsm_x4(uint32_t addr, uint32_t& r0, uint32_t& r1,
                                        uint32_t& r2, uint32_t& r3) {
    asm volatile("ldmatrix.sync.aligned.m8n8.x4.shared.b16 {%0,%1,%2,%3}, [%4];"
                 : "=r"(r0), "=r"(r1), "=r"(r2), "=r"(r3) : "r"(addr));
}
__device__ __forceinline__ void ldsm_x4_t(uint32_t addr, uint32_t& r0, uint32_t& r1,
                                          uint32_t& r2, uint32_t& r3) {
    asm volatile("ldmatrix.sync.aligned.m8n8.x4.trans.shared.b16 {%0,%1,%2,%3}, [%4];"
                 : "=r"(r0), "=r"(r1), "=r"(r2), "=r"(r3) : "r"(addr));
}
__device__ __forceinline__ void mma_f16(float& d0, float& d1, float& d2, float& d3,
                                        uint32_t a0, uint32_t a1, uint32_t a2, uint32_t a3,
                                        uint32_t b0, uint32_t b1) {
    asm volatile("mma.sync.aligned.m16n8k16.row.col.f32.f16.f16.f32 "
                 "{%0,%1,%2,%3},{%4,%5,%6,%7},{%8,%9},{%0,%1,%2,%3};"
                 : "+f"(d0), "+f"(d1), "+f"(d2), "+f"(d3)
                 : "r"(a0), "r"(a1), "r"(a2), "r"(a3), "r"(b0), "r"(b1));
}

// ---------------- LayerNorm ---------------------------------------------------
__device__ __forceinline__ float4 ln_compute(const float* __restrict__ in,
                                             const float* __restrict__ gamma,
                                             const float* __restrict__ beta)
{
    const int row = blockIdx.x;
    const float* xr = in + (size_t)row * DIM;
    const int t = threadIdx.x;

    float4 xv = *(const float4*)(xr + t * 4);
    float sum = xv.x + xv.y + xv.z + xv.w;
    float sq  = xv.x*xv.x + xv.y*xv.y + xv.z*xv.z + xv.w*xv.w;
    #pragma unroll
    for (int o = 16; o > 0; o >>= 1) {
        sum += __shfl_xor_sync(0xffffffffu, sum, o);
        sq  += __shfl_xor_sync(0xffffffffu, sq,  o);
    }
    __shared__ float s1[8], s2[8];
    const int warp = t >> 5;
    if ((t & 31) == 0) { s1[warp] = sum; s2[warp] = sq; }
    __syncthreads();
    float tot = 0.f, totq = 0.f;
    #pragma unroll
    for (int w = 0; w < 8; w++) { tot += s1[w]; totq += s2[w]; }
    const float mean = tot * (1.0f / DIM);
    const float var  = totq * (1.0f / DIM) - mean * mean;
    const float inv  = rsqrtf(var + EPS);
    float4 gv = *(const float4*)(gamma + t * 4);
    float4 bv = *(const float4*)(beta  + t * 4);
    float4 ov;
    ov.x = (xv.x - mean) * inv * gv.x + bv.x;
    ov.y = (xv.y - mean) * inv * gv.y + bv.y;
    ov.z = (xv.z - mean) * inv * gv.z + bv.z;
    ov.w = (xv.w - mean) * inv * gv.w + bv.w;
    return ov;
}

__global__ __launch_bounds__(256) void ln1_kernel(const float* __restrict__ x,
                                                  const float* __restrict__ g,
                                                  const float* __restrict__ b)
{
    if (blockIdx.x == 0 && threadIdx.x == 0) g_ticket = 0;  // reset attn queue
    float4 ov = ln_compute(x, g, b);
    __half2* dst = (__half2*)(g_xn + (size_t)blockIdx.x * DIM + threadIdx.x * 4);
    dst[0] = __floats2half2_rn(ov.x, ov.y);
    dst[1] = __floats2half2_rn(ov.z, ov.w);
}
__global__ __launch_bounds__(256) void ln2_kernel(const float* __restrict__ g,
                                                  const float* __restrict__ b,
                                                  float* __restrict__ out)
{
    float4 ov = ln_compute(g_proj, g, b);
    *(float4*)(out + (size_t)blockIdx.x * DIM + threadIdx.x * 4) = ov;
}

// ---------------- weight transpose+convert: f32 [R][C] -> f16 [C][R] ---------
__global__ __launch_bounds__(256) void transpose_h_kernel(const float* __restrict__ in,
                                                          __half* __restrict__ out,
                                                          int R, int C)
{
    __shared__ float t[32][33];
    const int c0 = blockIdx.x * 32, r0 = blockIdx.y * 32;
    const int tx = threadIdx.x & 31, ty = threadIdx.x >> 5;
    #pragma unroll
    for (int i = ty; i < 32; i += 8)
        t[i][tx] = in[(size_t)(r0 + i) * C + c0 + tx];
    __syncthreads();
    #pragma unroll
    for (int i = ty; i < 32; i += 8)
        out[(size_t)(c0 + i) * R + r0 + tx] = __float2half_rn(t[tx][i]);
}

// ---------------- fp16 HMMA GEMM (round-11 config, best measured) ------------
// BM=128, BN=256, BK=32 halves; 512 threads = 16 warps (4x4); warp tile 32x64.
#define GBM 128
#define GBN 256
#define GBK 32
#define A_STH 40
#define B_STH 40
#define A_FLH (128 * A_STH)            // 5120 halves
#define B_FLH (256 * B_STH)            // 10240 halves
#define G_STG_H (A_FLH + B_FLH)        // 15360 halves / stage
#define GEMM_SMEM (3 * G_STG_H * 2)    // 92160 B

template<typename OutT>
__global__ __launch_bounds__(512, 1) void gemm_f16_kernel(
    const __half* __restrict__ A, const __half* __restrict__ BT,
    OutT* __restrict__ C, int Ntot, int K)
{
    extern __shared__ __half smh[];
    const uint32_t smu = smem_u32(smh);

    const int tid = threadIdx.x;
    const int lane = tid & 31;
    const int wid = tid >> 5;             // 0..15
    const int warpM = wid >> 2;           // 0..3
    const int warpN = wid & 3;            // 0..3
    const int bm = blockIdx.y * GBM;
    const int bn = blockIdx.x * GBN;
    const int NCH = K / GBK;
    const int grp = lane >> 3, lr = lane & 7;

    const int am = tid >> 2;              // 0..127
    const int ac = (tid & 3) * 8;
    const __half* aG = A + (size_t)(bm + am) * K + ac;
    const uint32_t aDst = smu + (uint32_t)(am * A_STH + ac) * 2;
    const int bnr = tid >> 1;             // 0..255
    const int bc  = (tid & 1) * 16;
    const __half* bG = BT + (size_t)(bn + bnr) * K + bc;
    const uint32_t bDst = smu + (uint32_t)(A_FLH + bnr * B_STH + bc) * 2;

    float acc[2][8][4];
    #pragma unroll
    for (int i = 0; i < 2; i++)
        #pragma unroll
        for (int j = 0; j < 8; j++)
            #pragma unroll
            for (int r = 0; r < 4; r++) acc[i][j][r] = 0.f;

    #define GEMM_ISSUE(c, stg) do {                                           \
        const uint32_t _so = (uint32_t)(stg) * (G_STG_H * 2);                  \
        cpa16(aDst + _so, aG + (c) * GBK);                                     \
        const __half* _bg = bG + (c) * GBK;                                    \
        cpa16(bDst + _so,      _bg);                                           \
        cpa16(bDst + _so + 16, _bg + 8);                                       \
    } while (0)

    GEMM_ISSUE(0, 0); cpa_commit();
    GEMM_ISSUE(1, 1); cpa_commit();

    int stg = 0;
    for (int c = 0; c < NCH; c++) {
        if (c == NCH - 1) cpa_wait<0>(); else cpa_wait<1>();
        __syncthreads();

        {
            int nstg = stg + 2; if (nstg >= 3) nstg -= 3;
            if (c + 2 < NCH) GEMM_ISSUE(c + 2, nstg);
            cpa_commit();
        }

        const uint32_t aS = smu + (uint32_t)(stg * G_STG_H) * 2;
        const uint32_t bS = aS + A_FLH * 2;

        #pragma unroll
        for (int ks = 0; ks < 2; ks++) {
            uint32_t a[2][4];
            #pragma unroll
            for (int mt = 0; mt < 2; mt++) {
                int row = warpM * 32 + mt * 16 + lr + (grp & 1) * 8;
                int kc  = ks * 16 + (grp >> 1) * 8;
                ldsm_x4(aS + (uint32_t)(row * A_STH + kc) * 2,
                        a[mt][0], a[mt][1], a[mt][2], a[mt][3]);
            }
            uint32_t bb[4][4];
            #pragma unroll
            for (int np = 0; np < 4; np++) {
                int rn = warpN * 64 + np * 16 + lr + (grp >> 1) * 8;
                int kc = ks * 16 + (grp & 1) * 8;
                ldsm_x4(bS + (uint32_t)(rn * B_STH + kc) * 2,
                        bb[np][0], bb[np][1], bb[np][2], bb[np][3]);
            }
            #pragma unroll
            for (int mt = 0; mt < 2; mt++)
                #pragma unroll
                for (int np = 0; np < 4; np++)
                    #pragma unroll
                    for (int s = 0; s < 2; s++)
                        mma_f16(acc[mt][np*2+s][0], acc[mt][np*2+s][1],
                                acc[mt][np*2+s][2], acc[mt][np*2+s][3],
                                a[mt][0], a[mt][1], a[mt][2], a[mt][3],
                                bb[np][2*s], bb[np][2*s+1]);
        }

        if (++stg == 3) stg = 0;
    }

    #pragma unroll
    for (int mt = 0; mt < 2; mt++) {
        #pragma unroll
        for (int nt = 0; nt < 8; nt++) {
            const int row = bm + warpM * 32 + mt * 16 + (lane >> 2);
            const int col = bn + warpN * 64 + nt * 8 + (lane & 3) * 2;
            if (sizeof(OutT) == 2) {
                __half2* p0 = (__half2*)((__half*)C + (size_t)row * Ntot + col);
                __half2* p1 = (__half2*)((__half*)C + (size_t)(row + 8) * Ntot + col);
                *p0 = __floats2half2_rn(acc[mt][nt][0], acc[mt][nt][1]);
                *p1 = __floats2half2_rn(acc[mt][nt][2], acc[mt][nt][3]);
            } else {
                *(float2*)((float*)C + (size_t)row * Ntot + col) =
                    make_float2(acc[mt][nt][0], acc[mt][nt][1]);
                *(float2*)((float*)C + (size_t)(row + 8) * Ntot + col) =
                    make_float2(acc[mt][nt][2], acc[mt][nt][3]);
            }
        }
    }
    #undef GEMM_ISSUE
}

// ---------------- fp16 tensor-core causal ReLU attention (persistent) --------
// Work item = (qt4, bh): 256-query tile of one (b,h). 512 threads, 16 warps.
// Dynamic ticket queue (longest items first) removes wave quantization.
// Per item: round-11 structure — 64-key tiles, 3-buffer K+V ring, ldmatrix.
#define AQ_STH 72
#define AK_STH 72
#define AV_STH 72
#define AS_STH 72
#define KBUF_H (64 * AK_STH)            // 4608 halves
#define VBUF_H (64 * AV_STH)
#define OFFH_Q 0                        // 256*72 = 18432
#define OFFH_K 18432                    // 3*4608 = 13824
#define OFFH_V 32256                    // 3*4608 = 13824
#define OFFH_S 46080                    // 256*72 = 18432
#define ATTN_H 64512
#define ATTN_SMEM (ATTN_H * 2)          // 129024 B

__global__ __launch_bounds__(512, 1) void attn_mma_kernel()
{
    extern __shared__ __half smh[];
    __shared__ unsigned int s_ticket;
    const uint32_t smu = smem_u32(smh);
    const int tid  = threadIdx.x;
    const int lane = tid & 31;
    const int wid  = tid >> 5;            // 0..15
    const int ly = lane >> 2;
    const int lx = lane & 3;
    const int grp = lane >> 3, lr = lane & 7;

    const int ldr = tid >> 3;             // 0..63 (K/V staging row)
    const int ldc = (tid & 7) * 8;        // 8 halves (16B) per thread

    for (;;) {
        if (tid == 0) s_ticket = atomicAdd(&g_ticket, 1u);
        cpa_wait<0>();                    // drain prior item's groups
        __syncthreads();                  // publish ticket; smem safe to reuse
        const unsigned int item = s_ticket;
        if (item >= ATTN_ITEMS) break;

        const int qt4 = 7 - (int)(item >> 5);   // longest first
        const int bh  = (int)(item & 31u);
        const int b   = bh >> 4;
        const int h   = bh & 15;
        const int qi0 = qt4 * 256;
        const int kt_last = 4 * qt4 + 3;
        const int kt_diag = 4 * qt4 + (wid >> 2);

        const __half* qbase = g_qkv + (size_t)b * SEQ * QKV_N + h * DHEAD;
        const __half* kbase = qbase + INNER;
        const __half* vbase = qbase + 2 * INNER;

        #define ISSUE_KV(kt_, buf_) do {                                        \
            const __half* _sk = kbase + (size_t)((kt_) * 64 + ldr) * QKV_N + ldc;\
            cpa16(smu + (uint32_t)(OFFH_K + (buf_) * KBUF_H + ldr * AK_STH + ldc) * 2, _sk); \
            const __half* _sv = vbase + (size_t)((kt_) * 64 + ldr) * QKV_N + ldc;\
            cpa16(smu + (uint32_t)(OFFH_V + (buf_) * VBUF_H + ldr * AV_STH + ldc) * 2, _sv); \
        } while (0)

        // stage Q (256 rows; unscaled fp16; scale applied in S epilogue)
        {
            const int qr = tid >> 1;      // 0..255
            const int qc = (tid & 1) * 32;
            const __half* src = qbase + (size_t)(qi0 + qr) * QKV_N + qc;
            uint32_t dst = smu + (uint32_t)(OFFH_Q + qr * AQ_STH + qc) * 2;
            #pragma unroll
            for (int j = 0; j < 4; j++) cpa16(dst + j * 16, src + j * 8);
        }
        ISSUE_KV(0, 0); cpa_commit();
        ISSUE_KV(1, 1); cpa_commit();

        float oacc[8][4];
        #pragma unroll
        for (int nt = 0; nt < 8; nt++)
            #pragma unroll
            for (int r = 0; r < 4; r++) oacc[nt][r] = 0.f;

        __half* shw = smh + OFFH_S + (wid * 16 + ly) * AS_STH;
        const int qrow = qi0 + wid * 16 + ly;

        int stg = 0;
        for (int kt = 0; kt <= kt_last; kt++) {
            if (kt == kt_last) cpa_wait<0>(); else cpa_wait<1>();
            __syncthreads();              // Q + K/V(kt) visible; stage kt-1 free

            {
                int nstg = stg + 2; if (nstg >= 3) nstg -= 3;
                if (kt + 2 <= kt_last) ISSUE_KV(kt + 2, nstg);
                cpa_commit();
            }

            if (kt <= kt_diag) {
                // ---- S = Q K^T (K=64 -> 4 ks of 16)
                const uint32_t Kc = smu + (uint32_t)(OFFH_K + stg * KBUF_H) * 2;
                const uint32_t Qb = smu + (uint32_t)OFFH_Q * 2;
                float sacc[8][4];
                #pragma unroll
                for (int nt = 0; nt < 8; nt++)
                    #pragma unroll
                    for (int r = 0; r < 4; r++) sacc[nt][r] = 0.f;

                #pragma unroll
                for (int ks = 0; ks < 4; ks++) {
                    uint32_t a[4];
                    {
                        int row = wid * 16 + lr + (grp & 1) * 8;
                        int kc  = ks * 16 + (grp >> 1) * 8;
                        ldsm_x4(Qb + (uint32_t)(row * AQ_STH + kc) * 2,
                                a[0], a[1], a[2], a[3]);
                    }
                    #pragma unroll
                    for (int np = 0; np < 4; np++) {
                        uint32_t bb[4];
                        int rn = np * 16 + lr + (grp >> 1) * 8;
                        int kc = ks * 16 + (grp & 1) * 8;
                        ldsm_x4(Kc + (uint32_t)(rn * AK_STH + kc) * 2,
                                bb[0], bb[1], bb[2], bb[3]);
                        #pragma unroll
                        for (int s = 0; s < 2; s++)
                            mma_f16(sacc[np*2+s][0], sacc[np*2+s][1],
                                    sacc[np*2+s][2], sacc[np*2+s][3],
                                    a[0], a[1], a[2], a[3], bb[2*s], bb[2*s+1]);
                    }
                }

                // ---- scale+relu (+ mask on diagonal tile), fp16 -> smem S
                if (kt < kt_diag) {
                    #pragma unroll
                    for (int nt = 0; nt < 8; nt++) {
                        float v0 = fmaxf(sacc[nt][0], 0.f) * QSCALE;
                        float v1 = fmaxf(sacc[nt][1], 0.f) * QSCALE;
                        float v2 = fmaxf(sacc[nt][2], 0.f) * QSCALE;
                        float v3 = fmaxf(sacc[nt][3], 0.f) * QSCALE;
                        *(__half2*)(shw + nt * 8 + 2 * lx) = __floats2half2_rn(v0, v1);
                        *(__half2*)(shw + 8 * AS_STH + nt * 8 + 2 * lx) = __floats2half2_rn(v2, v3);
                    }
                } else {
                    #pragma unroll
                    for (int nt = 0; nt < 8; nt++) {
                        int j0 = kt * 64 + nt * 8 + 2 * lx;
                        float v0 = (j0     <= qrow    ) ? fmaxf(sacc[nt][0], 0.f) * QSCALE : 0.f;
                        float v1 = (j0 + 1 <= qrow    ) ? fmaxf(sacc[nt][1], 0.f) * QSCALE : 0.f;
                        float v2 = (j0     <= qrow + 8) ? fmaxf(sacc[nt][2], 0.f) * QSCALE : 0.f;
                        float v3 = (j0 + 1 <= qrow + 8) ? fmaxf(sacc[nt][3], 0.f) * QSCALE : 0.f;
                        *(__half2*)(shw + nt * 8 + 2 * lx) = __floats2half2_rn(v0, v1);
                        *(__half2*)(shw + 8 * AS_STH + nt * 8 + 2 * lx) = __floats2half2_rn(v2, v3);
                    }
                }
                __syncwarp();             // S rows are warp-private

                // ---- O += S*V (A = S non-trans; B = V via ldmatrix.trans)
                const uint32_t Sb = smu + (uint32_t)OFFH_S * 2;
                const uint32_t Vc = smu + (uint32_t)(OFFH_V + stg * VBUF_H) * 2;
                #pragma unroll
                for (int ks = 0; ks < 4; ks++) {
                    uint32_t a[4];
                    {
                        int row = wid * 16 + lr + (grp & 1) * 8;
                        int kc  = ks * 16 + (grp >> 1) * 8;
                        ldsm_x4(Sb + (uint32_t)(row * AS_STH + kc) * 2,
                                a[0], a[1], a[2], a[3]);
                    }
                    #pragma unroll
                    for (int np = 0; np < 4; np++) {
                        uint32_t bb[4];
                        int kr = ks * 16 + lr + (grp & 1) * 8;
                        int nc = np * 16 + (grp >> 1) * 8;
                        ldsm_x4_t(Vc + (uint32_t)(kr * AV_STH + nc) * 2,
                                  bb[0], bb[1], bb[2], bb[3]);
                        #pragma unroll
                        for (int s = 0; s < 2; s++)
                            mma_f16(oacc[np*2+s][0], oacc[np*2+s][1],
                                    oacc[np*2+s][2], oacc[np*2+s][3],
                                    a[0], a[1], a[2], a[3], bb[2*s], bb[2*s+1]);
                    }
                }
            }

            if (++stg == 3) stg = 0;
        }

        // ---- store O as fp16 (feeds fp16 out-projection)
        __half* ob = g_att + (size_t)(b * SEQ + qi0 + wid * 16 + ly) * INNER + h * DHEAD;
        #pragma unroll
        for (int nt = 0; nt < 8; nt++) {
            *(__half2*)(ob + nt * 8 + 2 * lx) =
                __floats2half2_rn(oacc[nt][0], oacc[nt][1]);
            *(__half2*)(ob + (size_t)8 * INNER + nt * 8 + 2 * lx) =
                __floats2half2_rn(oacc[nt][2], oacc[nt][3]);
        }
        #undef ISSUE_KV
    }
}

// ---------------- launch -----------------------------------------------------
extern "C" void kernel_launch(void* const* d_in, const int* in_sizes, int n_in,
                              void* d_out, int out_size)
{
    const float* x     = (const float*)d_in[0];
    const float* ln1_g = (const float*)d_in[1];
    const float* ln1_b = (const float*)d_in[2];
    const float* w_qkv = (const float*)d_in[3];
    const float* w_out = (const float*)d_in[4];
    const float* ln2_g = (const float*)d_in[5];
    const float* ln2_b = (const float*)d_in[6];
    float* out = (float*)d_out;

    cudaFuncSetAttribute(attn_mma_kernel,
                         cudaFuncAttributeMaxDynamicSharedMemorySize, ATTN_SMEM);
    cudaFuncSetAttribute(gemm_f16_kernel<__half>,
                         cudaFuncAttributeMaxDynamicSharedMemorySize, GEMM_SMEM);
    cudaFuncSetAttribute(gemm_f16_kernel<float>,
                         cudaFuncAttributeMaxDynamicSharedMemorySize, GEMM_SMEM);

    __half* wq;  cudaGetSymbolAddress((void**)&wq,  g_wq);
    __half* wo;  cudaGetSymbolAddress((void**)&wo,  g_wo);
    __half* xn;  cudaGetSymbolAddress((void**)&xn,  g_xn);
    __half* qkv; cudaGetSymbolAddress((void**)&qkv, g_qkv);
    __half* att; cudaGetSymbolAddress((void**)&att, g_att);
    float* proj; cudaGetSymbolAddress((void**)&proj, g_proj);

    ln1_kernel<<<ROWS, 256>>>(x, ln1_g, ln1_b);

    // weights: f32 [K][N] -> f16 [N][K]
    transpose_h_kernel<<<dim3(QKV_N / 32, DIM / 32), 256>>>(w_qkv, wq, DIM, QKV_N);
    transpose_h_kernel<<<dim3(DIM / 32, INNER / 32), 256>>>(w_out, wo, INNER, DIM);

    gemm_f16_kernel<__half><<<dim3(QKV_N / GBN, ROWS / GBM), 512, GEMM_SMEM>>>(
        xn, wq, qkv, QKV_N, DIM);

    attn_mma_kernel<<<152, 512, ATTN_SMEM>>>();

    gemm_f16_kernel<float><<<dim3(DIM / GBN, ROWS / GBM), 512, GEMM_SMEM>>>(
        att, wo, proj, DIM, INNER);

    ln2_kernel<<<ROWS, 256>>>(ln2_g, ln2_b, out);
}